// round 11
// baseline (speedup 1.0000x reference)
#include <cuda_runtime.h>

// Problem constants
#define N      6144
#define GRID   148
#define MAXR   48
// Kernel P (reduce): 1024 threads, 6 j's/thread, K+V in regs, 32 warps/SM.
#define TP     1024
#define JP     6
// Kernel W (write): 768 threads x 296 blocks (2/SM), 8 j's/thread, STG.128.
#define TW     768
#define GRIDW  296

// MUFU.EX2 forced via PTX.
__device__ __forceinline__ float ex2(float v) {
    float r;
    asm("ex2.approx.f32 %0, %1;" : "=f"(r) : "f"(v));
    return r;
}

// Per-row handoff P -> W: (g1x,g1y,g1z)*log2e in xyz, 1/rowsum in w.
__device__ float4 d_rowmeta[N];

struct SmemP {
    float sg[MAXR][3];       // current phase's g rows, pre-scaled by log2(e)
    float y2[MAXR][3];       // (a2 @ v2) rows from phase A
    float red[2][32][13];    // parity-buffered per-warp partials (12 used)
    float tot[2][12];        // parity-buffered block totals
    float sinv[2][3];        // parity-buffered 1/rowsum
};

// ---------------------------------------------------------------------------
// Kernel P: both matrices, reduction-only (no a1 writes).
//   Scalar math (packing proved neutral: not fma-bound). K/V in registers
//   (6 j's/thread -> 36 regs), T=1024 -> 32 warps/SM for latency cover.
//   3 rows/iter; parity-buffered two-barrier reduction.
// ---------------------------------------------------------------------------
__global__ void __launch_bounds__(TP, 1) reduce_kernel(
    const float* __restrict__ x,
    const float* __restrict__ wq1, const float* __restrict__ bq1,
    const float* __restrict__ wq2, const float* __restrict__ bq2,
    const float* __restrict__ wq3, const float* __restrict__ bq3,
    const float* __restrict__ wq4, const float* __restrict__ bq4,
    const float* __restrict__ wk1, const float* __restrict__ bk1,
    const float* __restrict__ wk2, const float* __restrict__ bk2,
    const float* __restrict__ wv1, const float* __restrict__ bv1,
    const float* __restrict__ wv2, const float* __restrict__ bv2,
    const float* __restrict__ wb,  const float* __restrict__ bb,
    float* __restrict__ b_out)     // [N, 3]
{
    __shared__ SmemP sm;

    const int t  = threadIdx.x;
    const int j0 = t * JP;
    const int r0 = (int)(((long long)N * blockIdx.x) / GRID);
    const int r1 = (int)(((long long)N * (blockIdx.x + 1)) / GRID);
    const int nr = r1 - r0;
    const float LOG2E = 1.4426950408889634f;

    float kx[JP], ky[JP], kz[JP], vx[JP], vy[JP], vz[JP];

    #pragma unroll
    for (int phase = 0; phase < 2; phase++) {
        const float* wk = phase ? wk1 : wk2;  const float* bk = phase ? bk1 : bk2;
        const float* wv = phase ? wv1 : wv2;  const float* bv = phase ? bv1 : bv2;
        const float* wA = phase ? wq1 : wq3;  const float* bA = phase ? bq1 : bq3;
        const float* wB = phase ? wq2 : wq4;  const float* bB = phase ? bq2 : bq4;

        {   // x slice reloaded per phase (keeps live range short)
            float xs[3 * JP];
            const float2* xp = (const float2*)(x + 3 * j0);   // 72B*t, 8B aligned
            #pragma unroll
            for (int q = 0; q < (3 * JP) / 2; q++) {
                float2 f = xp[q];
                xs[2*q] = f.x; xs[2*q+1] = f.y;
            }
            #pragma unroll
            for (int s = 0; s < JP; s++) {
                float X0 = xs[3*s], X1 = xs[3*s+1], X2 = xs[3*s+2];
                kx[s] = bk[0] + wk[0]*X0 + wk[1]*X1 + wk[2]*X2;
                ky[s] = bk[1] + wk[3]*X0 + wk[4]*X1 + wk[5]*X2;
                kz[s] = bk[2] + wk[6]*X0 + wk[7]*X1 + wk[8]*X2;
                vx[s] = bv[0] + wv[0]*X0 + wv[1]*X1 + wv[2]*X2;
                vy[s] = bv[1] + wv[3]*X0 + wv[4]*X1 + wv[5]*X2;
                vz[s] = bv[2] + wv[6]*X0 + wv[7]*X1 + wv[8]*X2;
            }
        }
        if (t < nr) {
            int i = r0 + t;
            float X0 = x[3*i], X1 = x[3*i+1], X2 = x[3*i+2];
            #pragma unroll
            for (int c = 0; c < 3; c++) {
                float v = (bA[c] + bB[c])
                        + (wA[c*3+0] + wB[c*3+0]) * X0
                        + (wA[c*3+1] + wB[c*3+1]) * X1
                        + (wA[c*3+2] + wB[c*3+2]) * X2;
                sm.sg[t][c] = v * LOG2E;
            }
        }
        __syncthreads();

        int par = 0;
        for (int ii = 0; ii < nr; ii += 3, par ^= 1) {
            int li[3];
            #pragma unroll
            for (int rr = 0; rr < 3; rr++) li[rr] = (ii + rr < nr) ? ii + rr : nr - 1;

            float g[3][3];
            #pragma unroll
            for (int rr = 0; rr < 3; rr++) {
                g[rr][0] = sm.sg[li[rr]][0];
                g[rr][1] = sm.sg[li[rr]][1];
                g[rr][2] = sm.sg[li[rr]][2];
            }

            float r[12];
            #pragma unroll
            for (int q = 0; q < 12; q++) r[q] = 0.f;

            #pragma unroll
            for (int s = 0; s < JP; s++) {
                float KX = kx[s], KY = ky[s], KZ = kz[s];
                float VX = vx[s], VY = vy[s], VZ = vz[s];
                #pragma unroll
                for (int rr = 0; rr < 3; rr++) {
                    float l = fmaf(g[rr][0], KX, fmaf(g[rr][1], KY, g[rr][2] * KZ));
                    float e = ex2(l);
                    r[4*rr+0] += e;
                    r[4*rr+1] = fmaf(e, VX, r[4*rr+1]);
                    r[4*rr+2] = fmaf(e, VY, r[4*rr+2]);
                    r[4*rr+3] = fmaf(e, VZ, r[4*rr+3]);
                }
            }
            #pragma unroll
            for (int o = 16; o > 0; o >>= 1) {
                #pragma unroll
                for (int q = 0; q < 12; q++)
                    r[q] += __shfl_xor_sync(0xffffffffu, r[q], o);
            }
            if ((t & 31) == 0) {
                int w = t >> 5;
                #pragma unroll
                for (int q = 0; q < 12; q++) sm.red[par][w][q] = r[q];
            }
            __syncthreads();
            if (t < 12 * 32) {   // stage 2: warp q reduces the 32 per-warp partials
                int q = t >> 5, w = t & 31;
                float v = sm.red[par][w][q];
                #pragma unroll
                for (int o = 16; o > 0; o >>= 1)
                    v += __shfl_xor_sync(0xffffffffu, v, o);
                if (w == 0) {
                    sm.tot[par][q] = v;
                    if (q == 0) sm.sinv[par][0] = 1.0f / v;
                    if (q == 4) sm.sinv[par][1] = 1.0f / v;
                    if (q == 8) sm.sinv[par][2] = 1.0f / v;
                }
            }
            __syncthreads();

            if ((t & 31) == 0 && (t >> 5) < 3) {
                int rr = t >> 5;
                if (ii + rr < nr) {
                    float inv = sm.sinv[par][rr];
                    if (phase == 0) {
                        sm.y2[ii+rr][0] = sm.tot[par][4*rr+1] * inv;
                        sm.y2[ii+rr][1] = sm.tot[par][4*rr+2] * inv;
                        sm.y2[ii+rr][2] = sm.tot[par][4*rr+3] * inv;
                    } else {
                        int i = r0 + ii + rr;
                        float4 m;
                        m.x = sm.sg[ii+rr][0];
                        m.y = sm.sg[ii+rr][1];
                        m.z = sm.sg[ii+rr][2];
                        m.w = inv;
                        d_rowmeta[i] = m;
                        float y0 = sm.tot[par][4*rr+1] * inv + sm.y2[ii+rr][0];
                        float y1 = sm.tot[par][4*rr+2] * inv + sm.y2[ii+rr][1];
                        float y2 = sm.tot[par][4*rr+3] * inv + sm.y2[ii+rr][2];
                        #pragma unroll
                        for (int c = 0; c < 3; c++)
                            b_out[i*3+c] = bb[c] + wb[c*3+0]*y0
                                                 + wb[c*3+1]*y1
                                                 + wb[c*3+2]*y2;
                    }
                }
            }
            // no trailing barrier — next iter uses the other parity buffers
        }
        __syncthreads();   // phase A sg/y2 reads complete before phase B refills
    }
}

// ---------------------------------------------------------------------------
// Kernel W: streaming a1 writer. Zero smem / shfl / barriers.
//   STG.128: thread t owns j in {4t..4t+3} and {3072+4t..3072+4t+3}; lanes
//   16B-consecutive -> perfect 512B/warp stores, half the store-issue cost
//   of STG.64. 296 blocks (2/SM) x 768 threads = 75% occupancy.
// ---------------------------------------------------------------------------
__global__ void __launch_bounds__(TW, 2) write_kernel(
    const float* __restrict__ x,
    const float* __restrict__ wk1, const float* __restrict__ bk1,
    float* __restrict__ a_out)     // [N, N]
{
    const int t  = threadIdx.x;
    const int r0 = (int)(((long long)N * blockIdx.x) / GRIDW);
    const int r1 = (int)(((long long)N * (blockIdx.x + 1)) / GRIDW);
    const int nr = r1 - r0;

    // K1 for 8 owned j's: j = 4t + h and 3072 + 4t + h, h = 0..3.
    float kx[8], ky[8], kz[8];
    #pragma unroll
    for (int s = 0; s < 2; s++) {
        int jb = 4 * t + s * 3072;
        #pragma unroll
        for (int h = 0; h < 4; h++) {
            int j = jb + h;
            float X0 = x[3*j], X1 = x[3*j+1], X2 = x[3*j+2];
            kx[4*s+h] = bk1[0] + wk1[0]*X0 + wk1[1]*X1 + wk1[2]*X2;
            ky[4*s+h] = bk1[1] + wk1[3]*X0 + wk1[4]*X1 + wk1[5]*X2;
            kz[4*s+h] = bk1[2] + wk1[6]*X0 + wk1[7]*X1 + wk1[8]*X2;
        }
    }

    for (int ii = 0; ii < nr; ii += 4) {
        float4 m[4];
        int    iv[4];
        #pragma unroll
        for (int rr = 0; rr < 4; rr++) {
            int l = (ii + rr < nr) ? ii + rr : nr - 1;   // clamp (benign dup)
            iv[rr] = r0 + l;
            m[rr]  = d_rowmeta[iv[rr]];                  // broadcast LDG
        }
        #pragma unroll
        for (int rr = 0; rr < 4; rr++) {
            const float gx = m[rr].x, gy = m[rr].y, gz = m[rr].z, inv = m[rr].w;
            float* rowp = a_out + (size_t)iv[rr] * N + 4 * t;
            #pragma unroll
            for (int s = 0; s < 2; s++) {
                float4 o;
                o.x = ex2(fmaf(gx, kx[4*s+0], fmaf(gy, ky[4*s+0], gz*kz[4*s+0]))) * inv;
                o.y = ex2(fmaf(gx, kx[4*s+1], fmaf(gy, ky[4*s+1], gz*kz[4*s+1]))) * inv;
                o.z = ex2(fmaf(gx, kx[4*s+2], fmaf(gy, ky[4*s+2], gz*kz[4*s+2]))) * inv;
                o.w = ex2(fmaf(gx, kx[4*s+3], fmaf(gy, ky[4*s+3], gz*kz[4*s+3]))) * inv;
                __stcs((float4*)(rowp + s * 3072), o);   // evict-first stream
            }
        }
    }
}

// ---------------------------------------------------------------------------
// Two launches: reduce (y2, b, rowmeta) -> write (a1).
// Output layout: a1 [N*N] followed by b [N*3].
// ---------------------------------------------------------------------------
extern "C" void kernel_launch(void* const* d_in, const int* in_sizes, int n_in,
                              void* d_out, int out_size)
{
    const float* x   = (const float*)d_in[0];
    const float* wq1 = (const float*)d_in[1];
    const float* bq1 = (const float*)d_in[2];
    const float* wq2 = (const float*)d_in[3];
    const float* bq2 = (const float*)d_in[4];
    const float* wq3 = (const float*)d_in[5];
    const float* bq3 = (const float*)d_in[6];
    const float* wq4 = (const float*)d_in[7];
    const float* bq4 = (const float*)d_in[8];
    const float* wk1 = (const float*)d_in[9];
    const float* bk1 = (const float*)d_in[10];
    const float* wk2 = (const float*)d_in[11];
    const float* bk2 = (const float*)d_in[12];
    const float* wv1 = (const float*)d_in[13];
    const float* bv1 = (const float*)d_in[14];
    const float* wv2 = (const float*)d_in[15];
    const float* bv2 = (const float*)d_in[16];
    const float* wb  = (const float*)d_in[17];
    const float* bb  = (const float*)d_in[18];

    float* out = (float*)d_out;
    float* a1  = out;                      // [N, N]
    float* b   = out + (size_t)N * N;      // [N, 3]

    reduce_kernel<<<GRID, TP>>>(
        x, wq1, bq1, wq2, bq2, wq3, bq3, wq4, bq4,
        wk1, bk1, wk2, bk2, wv1, bv1, wv2, bv2,
        wb, bb, b);

    write_kernel<<<GRIDW, TW>>>(x, wk1, bk1, a1);
}

// round 13
// speedup vs baseline: 1.0650x; 1.0650x over previous
#include <cuda_runtime.h>

// Problem constants
#define N      6144
#define MAXR   48
// Kernel P (reduce): 296 blocks (2/SM), 512 threads, j split in halves (JPH=6).
#define TPP    512
#define GRIDP  296
#define JPH    6
// Kernel W (write): 1024 threads x 148 blocks, interleaved j-pairs (R9 proven).
#define TW     1024
#define GRIDW  148

// MUFU.EX2 forced via PTX.
__device__ __forceinline__ float ex2(float v) {
    float r;
    asm("ex2.approx.f32 %0, %1;" : "=f"(r) : "f"(v));
    return r;
}

// Global scratch.
// d_part[phase][half][i][q]: raw partial [sum, ax, ay, az] of row i over one
//   j-half. phase 0 = matrix 2 (q3+q4/k2/v2), phase 1 = matrix 1 (q1+q2/k1/v1).
__device__ float  d_part[2][2][N][4];
// Per-row handoff to write kernel: (g1x,g1y,g1z)*log2e, 1/rowsum1.
__device__ float4 d_rowmeta[N];

// ---------------------------------------------------------------------------
// Kernel P: raw-partial reduction. 2 co-resident blocks per SM (j-halves);
//   barrier/shfl stalls of one block are hidden by the other block's math.
//   Per block: K/V of its j-half in registers (36 regs), both phases in
//   sequence, 3 rows/iter, ONE barrier per iteration (stage 2 runs in warps
//   0-2 on parity-buffered partials and stores raw sums to d_part).
// ---------------------------------------------------------------------------
__global__ void __launch_bounds__(TPP, 2) reduce_kernel(
    const float* __restrict__ x,
    const float* __restrict__ wq1, const float* __restrict__ bq1,
    const float* __restrict__ wq2, const float* __restrict__ bq2,
    const float* __restrict__ wq3, const float* __restrict__ bq3,
    const float* __restrict__ wq4, const float* __restrict__ bq4,
    const float* __restrict__ wk1, const float* __restrict__ bk1,
    const float* __restrict__ wk2, const float* __restrict__ bk2,
    const float* __restrict__ wv1, const float* __restrict__ bv1,
    const float* __restrict__ wv2, const float* __restrict__ bv2)
{
    __shared__ float sg[MAXR][3];        // g rows of current phase (log2e-scaled)
    __shared__ float red[2][16][13];     // parity-buffered per-warp partials

    const int t    = threadIdx.x;
    const int half = blockIdx.x & 1;
    const int rb   = blockIdx.x >> 1;            // 0..147
    const int r0 = (int)(((long long)N * rb) / 148);
    const int r1 = (int)(((long long)N * (rb + 1)) / 148);
    const int nr = r1 - r0;
    const int j0 = half * (N / 2) + t * JPH;
    const float LOG2E = 1.4426950408889634f;

    float kx[JPH], ky[JPH], kz[JPH], vx[JPH], vy[JPH], vz[JPH];

    #pragma unroll
    for (int phase = 0; phase < 2; phase++) {
        const float* wk = phase ? wk1 : wk2;  const float* bk = phase ? bk1 : bk2;
        const float* wv = phase ? wv1 : wv2;  const float* bv = phase ? bv1 : bv2;
        const float* wA = phase ? wq1 : wq3;  const float* bA = phase ? bq1 : bq3;
        const float* wB = phase ? wq2 : wq4;  const float* bB = phase ? bq2 : bq4;

        {   // K/V of this j-half from x (float2 loads; 3*j0 is even)
            float xs[3 * JPH];
            const float2* xp = (const float2*)(x + 3 * j0);
            #pragma unroll
            for (int q = 0; q < (3 * JPH) / 2; q++) {
                float2 f = xp[q];
                xs[2*q] = f.x; xs[2*q+1] = f.y;
            }
            #pragma unroll
            for (int s = 0; s < JPH; s++) {
                float X0 = xs[3*s], X1 = xs[3*s+1], X2 = xs[3*s+2];
                kx[s] = bk[0] + wk[0]*X0 + wk[1]*X1 + wk[2]*X2;
                ky[s] = bk[1] + wk[3]*X0 + wk[4]*X1 + wk[5]*X2;
                kz[s] = bk[2] + wk[6]*X0 + wk[7]*X1 + wk[8]*X2;
                vx[s] = bv[0] + wv[0]*X0 + wv[1]*X1 + wv[2]*X2;
                vy[s] = bv[1] + wv[3]*X0 + wv[4]*X1 + wv[5]*X2;
                vz[s] = bv[2] + wv[6]*X0 + wv[7]*X1 + wv[8]*X2;
            }
        }
        if (t < nr) {
            int i = r0 + t;
            float X0 = x[3*i], X1 = x[3*i+1], X2 = x[3*i+2];
            #pragma unroll
            for (int c = 0; c < 3; c++) {
                float v = (bA[c] + bB[c])
                        + (wA[c*3+0] + wB[c*3+0]) * X0
                        + (wA[c*3+1] + wB[c*3+1]) * X1
                        + (wA[c*3+2] + wB[c*3+2]) * X2;
                sg[t][c] = v * LOG2E;
            }
        }
        __syncthreads();   // sg ready; also fences previous phase's red reads

        int par = 0;
        for (int ii = 0; ii < nr; ii += 3, par ^= 1) {
            int li[3];
            #pragma unroll
            for (int rr = 0; rr < 3; rr++) li[rr] = (ii + rr < nr) ? ii + rr : nr - 1;

            float g[3][3];
            #pragma unroll
            for (int rr = 0; rr < 3; rr++) {
                g[rr][0] = sg[li[rr]][0];
                g[rr][1] = sg[li[rr]][1];
                g[rr][2] = sg[li[rr]][2];
            }

            float r[12];
            #pragma unroll
            for (int q = 0; q < 12; q++) r[q] = 0.f;

            #pragma unroll
            for (int s = 0; s < JPH; s++) {
                float KX = kx[s], KY = ky[s], KZ = kz[s];
                float VX = vx[s], VY = vy[s], VZ = vz[s];
                #pragma unroll
                for (int rr = 0; rr < 3; rr++) {
                    float l = fmaf(g[rr][0], KX, fmaf(g[rr][1], KY, g[rr][2] * KZ));
                    float e = ex2(l);
                    r[4*rr+0] += e;
                    r[4*rr+1] = fmaf(e, VX, r[4*rr+1]);
                    r[4*rr+2] = fmaf(e, VY, r[4*rr+2]);
                    r[4*rr+3] = fmaf(e, VZ, r[4*rr+3]);
                }
            }
            #pragma unroll
            for (int o = 16; o > 0; o >>= 1) {
                #pragma unroll
                for (int q = 0; q < 12; q++)
                    r[q] += __shfl_xor_sync(0xffffffffu, r[q], o);
            }
            if ((t & 31) == 0) {
                int w = t >> 5;
                #pragma unroll
                for (int q = 0; q < 12; q++) red[par][w][q] = r[q];
            }
            __syncthreads();   // the ONLY barrier this iteration

            // Stage 2 in warps 0-2 (warp rr owns row ii+rr): each 8-lane group
            // reduces the 16 per-warp partials of quantity 4*rr+qq, stores RAW
            // partials to d_part (no division). Parity buffering makes a
            // trailing barrier unnecessary.
            if (t < 96) {
                int rr = t >> 5, l = t & 31;
                if (ii + rr < nr) {
                    int qq = l >> 3, w = l & 7;
                    int q  = 4 * rr + qq;            // <-- the R12 bug fix
                    float v = red[par][w][q] + red[par][w + 8][q];
                    v += __shfl_xor_sync(0xffffffffu, v, 4);
                    v += __shfl_xor_sync(0xffffffffu, v, 2);
                    v += __shfl_xor_sync(0xffffffffu, v, 1);
                    if (w == 0)
                        d_part[phase][half][r0 + ii + rr][qq] = v;
                }
            }
        }
        __syncthreads();   // all red/sg reads done before next phase refills
    }
}

// ---------------------------------------------------------------------------
// Kernel C: per-row combine. Merges the two j-half partials of both phases,
//   computes y2, the fused final Linear b_i, and d_rowmeta for the writer.
// ---------------------------------------------------------------------------
__global__ void combine_kernel(
    const float* __restrict__ x,
    const float* __restrict__ wq1, const float* __restrict__ bq1,
    const float* __restrict__ wq2, const float* __restrict__ bq2,
    const float* __restrict__ wb,  const float* __restrict__ bb,
    float* __restrict__ b_out)     // [N, 3]
{
    int i = blockIdx.x * blockDim.x + threadIdx.x;
    if (i >= N) return;
    const float LOG2E = 1.4426950408889634f;

    // Phase 0 = matrix 2 -> y2
    float s2  = d_part[0][0][i][0] + d_part[0][1][i][0];
    float inv2 = 1.0f / s2;
    float y2x = (d_part[0][0][i][1] + d_part[0][1][i][1]) * inv2;
    float y2y = (d_part[0][0][i][2] + d_part[0][1][i][2]) * inv2;
    float y2z = (d_part[0][0][i][3] + d_part[0][1][i][3]) * inv2;

    // Phase 1 = matrix 1 -> (a1@v1) row + inv for the writer
    float s1  = d_part[1][0][i][0] + d_part[1][1][i][0];
    float inv1 = 1.0f / s1;
    float t1x = (d_part[1][0][i][1] + d_part[1][1][i][1]) * inv1;
    float t1y = (d_part[1][0][i][2] + d_part[1][1][i][2]) * inv1;
    float t1z = (d_part[1][0][i][3] + d_part[1][1][i][3]) * inv1;

    // g1 row (combined q1+q2), log2e-scaled, for the writer's recompute.
    float X0 = x[3*i], X1 = x[3*i+1], X2 = x[3*i+2];
    float g1[3];
    #pragma unroll
    for (int c = 0; c < 3; c++) {
        g1[c] = ((bq1[c] + bq2[c])
              + (wq1[c*3+0] + wq2[c*3+0]) * X0
              + (wq1[c*3+1] + wq2[c*3+1]) * X1
              + (wq1[c*3+2] + wq2[c*3+2]) * X2) * LOG2E;
    }
    float4 m; m.x = g1[0]; m.y = g1[1]; m.z = g1[2]; m.w = inv1;
    d_rowmeta[i] = m;

    // b_i = Wb((a1@v1)_i + y2_i) + bb
    float y0 = t1x + y2x, y1 = t1y + y2y, yz = t1z + y2z;
    #pragma unroll
    for (int c = 0; c < 3; c++)
        b_out[i*3+c] = bb[c] + wb[c*3+0]*y0 + wb[c*3+1]*y1 + wb[c*3+2]*yz;
}

// ---------------------------------------------------------------------------
// Kernel W: streaming a1 writer (R9-proven form). Zero smem/shfl/barriers.
//   Interleaved ownership: thread t owns j-pairs {2t + s*2048}; STG.64 lanes
//   8B-consecutive -> perfect 128B wavefronts. __stcs evict-first stream.
// ---------------------------------------------------------------------------
__global__ void __launch_bounds__(TW, 1) write_kernel(
    const float* __restrict__ x,
    const float* __restrict__ wk1, const float* __restrict__ bk1,
    float* __restrict__ a_out)     // [N, N]
{
    const int t  = threadIdx.x;
    const int r0 = (int)(((long long)N * blockIdx.x) / GRIDW);
    const int r1 = (int)(((long long)N * (blockIdx.x + 1)) / GRIDW);
    const int nr = r1 - r0;

    // K1 for the 6 owned j's: j = 2t + s*2048 + {0,1}, s = 0..2.
    float kx[6], ky[6], kz[6];
    #pragma unroll
    for (int s = 0; s < 3; s++) {
        int jbase = 2 * t + s * 2048;
        #pragma unroll
        for (int h = 0; h < 2; h++) {
            int j = jbase + h;
            float X0 = x[3*j], X1 = x[3*j+1], X2 = x[3*j+2];
            kx[2*s+h] = bk1[0] + wk1[0]*X0 + wk1[1]*X1 + wk1[2]*X2;
            ky[2*s+h] = bk1[1] + wk1[3]*X0 + wk1[4]*X1 + wk1[5]*X2;
            kz[2*s+h] = bk1[2] + wk1[6]*X0 + wk1[7]*X1 + wk1[8]*X2;
        }
    }

    for (int ii = 0; ii < nr; ii += 4) {
        float4 m[4];
        int    iv[4];
        #pragma unroll
        for (int rr = 0; rr < 4; rr++) {
            int l = (ii + rr < nr) ? ii + rr : nr - 1;   // clamp (benign dup)
            iv[rr] = r0 + l;
            m[rr]  = d_rowmeta[iv[rr]];                  // broadcast LDG
        }
        #pragma unroll
        for (int rr = 0; rr < 4; rr++) {
            const float gx = m[rr].x, gy = m[rr].y, gz = m[rr].z, inv = m[rr].w;
            float* rowp = a_out + (size_t)iv[rr] * N + 2 * t;
            #pragma unroll
            for (int s = 0; s < 3; s++) {
                float l0 = fmaf(gx, kx[2*s+0], fmaf(gy, ky[2*s+0], gz * kz[2*s+0]));
                float l1 = fmaf(gx, kx[2*s+1], fmaf(gy, ky[2*s+1], gz * kz[2*s+1]));
                float2 o;
                o.x = ex2(l0) * inv;
                o.y = ex2(l1) * inv;
                __stcs((float2*)(rowp + s * 2048), o);   // evict-first stream
            }
        }
    }
}

// ---------------------------------------------------------------------------
// Three launches: reduce (raw partials) -> combine (y2, b, rowmeta) -> write.
// Output layout: a1 [N*N] followed by b [N*3].
// ---------------------------------------------------------------------------
extern "C" void kernel_launch(void* const* d_in, const int* in_sizes, int n_in,
                              void* d_out, int out_size)
{
    const float* x   = (const float*)d_in[0];
    const float* wq1 = (const float*)d_in[1];
    const float* bq1 = (const float*)d_in[2];
    const float* wq2 = (const float*)d_in[3];
    const float* bq2 = (const float*)d_in[4];
    const float* wq3 = (const float*)d_in[5];
    const float* bq3 = (const float*)d_in[6];
    const float* wq4 = (const float*)d_in[7];
    const float* bq4 = (const float*)d_in[8];
    const float* wk1 = (const float*)d_in[9];
    const float* bk1 = (const float*)d_in[10];
    const float* wk2 = (const float*)d_in[11];
    const float* bk2 = (const float*)d_in[12];
    const float* wv1 = (const float*)d_in[13];
    const float* bv1 = (const float*)d_in[14];
    const float* wv2 = (const float*)d_in[15];
    const float* bv2 = (const float*)d_in[16];
    const float* wb  = (const float*)d_in[17];
    const float* bb  = (const float*)d_in[18];

    float* out = (float*)d_out;
    float* a1  = out;                      // [N, N]
    float* b   = out + (size_t)N * N;      // [N, 3]

    reduce_kernel<<<GRIDP, TPP>>>(
        x, wq1, bq1, wq2, bq2, wq3, bq3, wq4, bq4,
        wk1, bk1, wk2, bk2, wv1, bv1, wv2, bv2);

    combine_kernel<<<(N + 255) / 256, 256>>>(
        x, wq1, bq1, wq2, bq2, wb, bb, b);

    write_kernel<<<GRIDW, TW>>>(x, wk1, bk1, a1);
}

// round 14
// speedup vs baseline: 1.3383x; 1.2566x over previous
#include <cuda_runtime.h>

// Problem constants
#define N      6144
#define GRID   148      // reduce/write: one block per SM
#define TP     512      // reduce threads (16 warps); lane-contiguous j slices
#define JP     12       // j's per thread (N / TP)
#define NW     16       // warps per reduce block
#define TW     1024     // write threads

// MUFU.EX2 forced via PTX.
__device__ __forceinline__ float ex2(float v) {
    float r;
    asm("ex2.approx.f32 %0, %1;" : "=f"(r) : "f"(v));
    return r;
}

// Global scratch.
// d_part[phase][i][w]: per-warp raw partial (sum, ax, ay, az) of row i over
//   warp w's 384-j slice. phase 0 = matrix 2, phase 1 = matrix 1.
__device__ float4 d_part[2][N][NW];
// Per-row handoff to the write kernel: (g1x,g1y,g1z)*log2e, 1/rowsum1.
__device__ float4 d_rowmeta[N];

// ---------------------------------------------------------------------------
// Kernel P: warp-autonomous partial reduction. NO barriers, NO smem.
//   Each warp: K/V for its 384-j slice in registers; loops over ALL rows of
//   the block; per row: g from registers (log2e pre-folded), 12-j mainloop,
//   private 5-step shuffle tree of 4 quantities, lane0 STG.128 partial.
// ---------------------------------------------------------------------------
__global__ void __launch_bounds__(TP, 1) reduce_kernel(
    const float* __restrict__ x,
    const float* __restrict__ wq1, const float* __restrict__ bq1,
    const float* __restrict__ wq2, const float* __restrict__ bq2,
    const float* __restrict__ wq3, const float* __restrict__ bq3,
    const float* __restrict__ wq4, const float* __restrict__ bq4,
    const float* __restrict__ wk1, const float* __restrict__ bk1,
    const float* __restrict__ wk2, const float* __restrict__ bk2,
    const float* __restrict__ wv1, const float* __restrict__ bv1,
    const float* __restrict__ wv2, const float* __restrict__ bv2)
{
    const int t  = threadIdx.x;
    const int w  = t >> 5;
    const int l  = t & 31;
    const int j0 = t * JP;
    const int r0 = (int)(((long long)N * blockIdx.x) / GRID);
    const int r1 = (int)(((long long)N * (blockIdx.x + 1)) / GRID);
    const float LOG2E = 1.4426950408889634f;

    float kx[JP], ky[JP], kz[JP], vx[JP], vy[JP], vz[JP];

    #pragma unroll
    for (int phase = 0; phase < 2; phase++) {
        const float* wk = phase ? wk1 : wk2;  const float* bk = phase ? bk1 : bk2;
        const float* wv = phase ? wv1 : wv2;  const float* bv = phase ? bv1 : bv2;
        const float* wA = phase ? wq1 : wq3;  const float* bA = phase ? bq1 : bq3;
        const float* wB = phase ? wq2 : wq4;  const float* bB = phase ? bq2 : bq4;

        // Combined g weights, log2(e) pre-folded (held in 12 registers).
        float wg[9], bg[3];
        #pragma unroll
        for (int c = 0; c < 3; c++) {
            wg[c*3+0] = (wA[c*3+0] + wB[c*3+0]) * LOG2E;
            wg[c*3+1] = (wA[c*3+1] + wB[c*3+1]) * LOG2E;
            wg[c*3+2] = (wA[c*3+2] + wB[c*3+2]) * LOG2E;
            bg[c]     = (bA[c] + bB[c]) * LOG2E;
        }

        {   // K/V of this thread's 12 j's from x (float4 loads, 16B aligned).
            float xs[3 * JP];
            const float4* xp = (const float4*)(x + 3 * j0);
            #pragma unroll
            for (int q = 0; q < (3 * JP) / 4; q++) {
                float4 f = xp[q];
                xs[4*q] = f.x; xs[4*q+1] = f.y; xs[4*q+2] = f.z; xs[4*q+3] = f.w;
            }
            #pragma unroll
            for (int s = 0; s < JP; s++) {
                float X0 = xs[3*s], X1 = xs[3*s+1], X2 = xs[3*s+2];
                kx[s] = bk[0] + wk[0]*X0 + wk[1]*X1 + wk[2]*X2;
                ky[s] = bk[1] + wk[3]*X0 + wk[4]*X1 + wk[5]*X2;
                kz[s] = bk[2] + wk[6]*X0 + wk[7]*X1 + wk[8]*X2;
                vx[s] = bv[0] + wv[0]*X0 + wv[1]*X1 + wv[2]*X2;
                vy[s] = bv[1] + wv[3]*X0 + wv[4]*X1 + wv[5]*X2;
                vz[s] = bv[2] + wv[6]*X0 + wv[7]*X1 + wv[8]*X2;
            }
        }

        // Every warp covers every row with its own j-slice; fully independent.
        for (int i = r0; i < r1; i++) {
            float X0 = __ldg(x + 3*i), X1 = __ldg(x + 3*i + 1), X2 = __ldg(x + 3*i + 2);
            float gx = bg[0] + wg[0]*X0 + wg[1]*X1 + wg[2]*X2;
            float gy = bg[1] + wg[3]*X0 + wg[4]*X1 + wg[5]*X2;
            float gz = bg[2] + wg[6]*X0 + wg[7]*X1 + wg[8]*X2;

            float r0a = 0.f, r1a = 0.f, r2a = 0.f, r3a = 0.f;
            #pragma unroll
            for (int s = 0; s < JP; s++) {
                float lg = fmaf(gx, kx[s], fmaf(gy, ky[s], gz * kz[s]));
                float e  = ex2(lg);
                r0a += e;
                r1a = fmaf(e, vx[s], r1a);
                r2a = fmaf(e, vy[s], r2a);
                r3a = fmaf(e, vz[s], r3a);
            }
            // Private warp tree (5 steps x 4 quantities). No cross-warp sync.
            #pragma unroll
            for (int o = 16; o > 0; o >>= 1) {
                r0a += __shfl_xor_sync(0xffffffffu, r0a, o);
                r1a += __shfl_xor_sync(0xffffffffu, r1a, o);
                r2a += __shfl_xor_sync(0xffffffffu, r2a, o);
                r3a += __shfl_xor_sync(0xffffffffu, r3a, o);
            }
            if (l == 0) {
                float4 p; p.x = r0a; p.y = r1a; p.z = r2a; p.w = r3a;
                d_part[phase][i][w] = p;
            }
        }
    }
}

// ---------------------------------------------------------------------------
// Kernel C: per-row combine. Sums the 16 warp partials of both phases,
//   computes y2, the fused final Linear b_i, and d_rowmeta for the writer.
// ---------------------------------------------------------------------------
__global__ void combine_kernel(
    const float* __restrict__ x,
    const float* __restrict__ wq1, const float* __restrict__ bq1,
    const float* __restrict__ wq2, const float* __restrict__ bq2,
    const float* __restrict__ wb,  const float* __restrict__ bb,
    float* __restrict__ b_out)     // [N, 3]
{
    int i = blockIdx.x * blockDim.x + threadIdx.x;
    if (i >= N) return;
    const float LOG2E = 1.4426950408889634f;

    // Phase 0 = matrix 2 -> y2
    float s2 = 0.f, a2x = 0.f, a2y = 0.f, a2z = 0.f;
    #pragma unroll
    for (int w = 0; w < NW; w++) {
        float4 p = d_part[0][i][w];
        s2 += p.x; a2x += p.y; a2y += p.z; a2z += p.w;
    }
    float inv2 = 1.0f / s2;

    // Phase 1 = matrix 1 -> (a1@v1) row + inv for the writer
    float s1 = 0.f, a1x = 0.f, a1y = 0.f, a1z = 0.f;
    #pragma unroll
    for (int w = 0; w < NW; w++) {
        float4 p = d_part[1][i][w];
        s1 += p.x; a1x += p.y; a1y += p.z; a1z += p.w;
    }
    float inv1 = 1.0f / s1;

    // g1 row (combined q1+q2), log2e-scaled, for the writer's recompute.
    float X0 = x[3*i], X1 = x[3*i+1], X2 = x[3*i+2];
    float g1[3];
    #pragma unroll
    for (int c = 0; c < 3; c++) {
        g1[c] = ((bq1[c] + bq2[c])
              + (wq1[c*3+0] + wq2[c*3+0]) * X0
              + (wq1[c*3+1] + wq2[c*3+1]) * X1
              + (wq1[c*3+2] + wq2[c*3+2]) * X2) * LOG2E;
    }
    float4 m; m.x = g1[0]; m.y = g1[1]; m.z = g1[2]; m.w = inv1;
    d_rowmeta[i] = m;

    // b_i = Wb((a1@v1)_i + y2_i) + bb
    float y0 = a1x * inv1 + a2x * inv2;
    float y1 = a1y * inv1 + a2y * inv2;
    float yz = a1z * inv1 + a2z * inv2;
    #pragma unroll
    for (int c = 0; c < 3; c++)
        b_out[i*3+c] = bb[c] + wb[c*3+0]*y0 + wb[c*3+1]*y1 + wb[c*3+2]*yz;
}

// ---------------------------------------------------------------------------
// Kernel W: streaming a1 writer (R9-proven form, untouched). Zero smem /
//   shfl / barriers. Interleaved ownership: thread t owns j-pairs
//   {2t + s*2048}; STG.64 lanes 8B-consecutive -> perfect 128B wavefronts.
// ---------------------------------------------------------------------------
__global__ void __launch_bounds__(TW, 1) write_kernel(
    const float* __restrict__ x,
    const float* __restrict__ wk1, const float* __restrict__ bk1,
    float* __restrict__ a_out)     // [N, N]
{
    const int t  = threadIdx.x;
    const int r0 = (int)(((long long)N * blockIdx.x) / GRID);
    const int r1 = (int)(((long long)N * (blockIdx.x + 1)) / GRID);
    const int nr = r1 - r0;

    // K1 for the 6 owned j's: j = 2t + s*2048 + {0,1}, s = 0..2.
    float kx[6], ky[6], kz[6];
    #pragma unroll
    for (int s = 0; s < 3; s++) {
        int jbase = 2 * t + s * 2048;
        #pragma unroll
        for (int h = 0; h < 2; h++) {
            int j = jbase + h;
            float X0 = x[3*j], X1 = x[3*j+1], X2 = x[3*j+2];
            kx[2*s+h] = bk1[0] + wk1[0]*X0 + wk1[1]*X1 + wk1[2]*X2;
            ky[2*s+h] = bk1[1] + wk1[3]*X0 + wk1[4]*X1 + wk1[5]*X2;
            kz[2*s+h] = bk1[2] + wk1[6]*X0 + wk1[7]*X1 + wk1[8]*X2;
        }
    }

    for (int ii = 0; ii < nr; ii += 4) {
        float4 m[4];
        int    iv[4];
        #pragma unroll
        for (int rr = 0; rr < 4; rr++) {
            int lcl = (ii + rr < nr) ? ii + rr : nr - 1;  // clamp (benign dup)
            iv[rr] = r0 + lcl;
            m[rr]  = d_rowmeta[iv[rr]];                   // broadcast LDG
        }
        #pragma unroll
        for (int rr = 0; rr < 4; rr++) {
            const float gx = m[rr].x, gy = m[rr].y, gz = m[rr].z, inv = m[rr].w;
            float* rowp = a_out + (size_t)iv[rr] * N + 2 * t;
            #pragma unroll
            for (int s = 0; s < 3; s++) {
                float l0 = fmaf(gx, kx[2*s+0], fmaf(gy, ky[2*s+0], gz * kz[2*s+0]));
                float l1 = fmaf(gx, kx[2*s+1], fmaf(gy, ky[2*s+1], gz * kz[2*s+1]));
                float2 o;
                o.x = ex2(l0) * inv;
                o.y = ex2(l1) * inv;
                __stcs((float2*)(rowp + s * 2048), o);    // evict-first stream
            }
        }
    }
}

// ---------------------------------------------------------------------------
// Three launches: reduce (warp partials) -> combine (y2, b, rowmeta) -> write.
// Output layout: a1 [N*N] followed by b [N*3].
// ---------------------------------------------------------------------------
extern "C" void kernel_launch(void* const* d_in, const int* in_sizes, int n_in,
                              void* d_out, int out_size)
{
    const float* x   = (const float*)d_in[0];
    const float* wq1 = (const float*)d_in[1];
    const float* bq1 = (const float*)d_in[2];
    const float* wq2 = (const float*)d_in[3];
    const float* bq2 = (const float*)d_in[4];
    const float* wq3 = (const float*)d_in[5];
    const float* bq3 = (const float*)d_in[6];
    const float* wq4 = (const float*)d_in[7];
    const float* bq4 = (const float*)d_in[8];
    const float* wk1 = (const float*)d_in[9];
    const float* bk1 = (const float*)d_in[10];
    const float* wk2 = (const float*)d_in[11];
    const float* bk2 = (const float*)d_in[12];
    const float* wv1 = (const float*)d_in[13];
    const float* bv1 = (const float*)d_in[14];
    const float* wv2 = (const float*)d_in[15];
    const float* bv2 = (const float*)d_in[16];
    const float* wb  = (const float*)d_in[17];
    const float* bb  = (const float*)d_in[18];

    float* out = (float*)d_out;
    float* a1  = out;                      // [N, N]
    float* b   = out + (size_t)N * N;      // [N, 3]

    reduce_kernel<<<GRID, TP>>>(
        x, wq1, bq1, wq2, bq2, wq3, bq3, wq4, bq4,
        wk1, bk1, wk2, bk2, wv1, bv1, wv2, bv2);

    combine_kernel<<<(N + 255) / 256, 256>>>(
        x, wq1, bq1, wq2, bq2, wb, bb, b);

    write_kernel<<<GRID, TW>>>(x, wk1, bk1, a1);
}

// round 15
// speedup vs baseline: 1.4682x; 1.0971x over previous
#include <cuda_runtime.h>

// Problem constants
#define N      6144
#define GRID   148      // one block per SM
#define TP     512      // reduce threads (16 warps)
#define JP     12       // j's per thread (6 packed pairs)
#define NW     16       // warps per reduce block
#define MAXR   48
#define TW     1024     // write threads

typedef unsigned long long u64;

// MUFU.EX2 forced via PTX.
__device__ __forceinline__ float ex2(float v) {
    float r;
    asm("ex2.approx.f32 %0, %1;" : "=f"(r) : "f"(v));
    return r;
}
// Packed f32x2 ops (FFMA2/FADD2/FMUL2 — only reachable via PTX).
__device__ __forceinline__ u64 pk2(float lo, float hi) {
    u64 r; asm("mov.b64 %0, {%1,%2};" : "=l"(r) : "f"(lo), "f"(hi)); return r;
}
__device__ __forceinline__ void upk2(u64 v, float& lo, float& hi) {
    asm("mov.b64 {%0,%1}, %2;" : "=f"(lo), "=f"(hi) : "l"(v));
}
__device__ __forceinline__ u64 fma2_(u64 a, u64 b, u64 c) {
    u64 r; asm("fma.rn.f32x2 %0, %1, %2, %3;" : "=l"(r) : "l"(a), "l"(b), "l"(c)); return r;
}
__device__ __forceinline__ u64 mul2_(u64 a, u64 b) {
    u64 r; asm("mul.rn.f32x2 %0, %1, %2;" : "=l"(r) : "l"(a), "l"(b)); return r;
}
__device__ __forceinline__ u64 add2_(u64 a, u64 b) {
    u64 r; asm("add.rn.f32x2 %0, %1, %2;" : "=l"(r) : "l"(a), "l"(b)); return r;
}

// Per-row handoff to the write kernel: (g1x,g1y,g1z)*log2e, 1/rowsum1.
__device__ float4 d_rowmeta[N];

// ---------------------------------------------------------------------------
// Kernel P: warp-autonomous partial reduction + in-block combine.
//   Each warp: packed K/V for its 384-j slice in registers; loops over ALL
//   rows of the block; per row: packed f32x2 mainloop, private shuffle tree,
//   lane0 stores the partial to SMEM. After both phases: ONE barrier, then
//   threads t<nr combine the 16 warp partials of both phases in-block and
//   emit d_rowmeta + b_out directly (no combine kernel, no global partials).
// ---------------------------------------------------------------------------
__global__ void __launch_bounds__(TP, 1) reduce_kernel(
    const float* __restrict__ x,
    const float* __restrict__ wq1, const float* __restrict__ bq1,
    const float* __restrict__ wq2, const float* __restrict__ bq2,
    const float* __restrict__ wq3, const float* __restrict__ bq3,
    const float* __restrict__ wq4, const float* __restrict__ bq4,
    const float* __restrict__ wk1, const float* __restrict__ bk1,
    const float* __restrict__ wk2, const float* __restrict__ bk2,
    const float* __restrict__ wv1, const float* __restrict__ bv1,
    const float* __restrict__ wv2, const float* __restrict__ bv2,
    const float* __restrict__ wb,  const float* __restrict__ bb,
    float* __restrict__ b_out)     // [N, 3]
{
    // Bank-padded partial store: [phase][row][warp] (pad 16->17 kills the
    // 32-way conflict on the combine read).
    __shared__ float4 ps[2][MAXR][NW + 1];

    const int t  = threadIdx.x;
    const int w  = t >> 5;
    const int l  = t & 31;
    const int j0 = t * JP;
    const int r0 = (int)(((long long)N * blockIdx.x) / GRID);
    const int r1 = (int)(((long long)N * (blockIdx.x + 1)) / GRID);
    const int nr = r1 - r0;
    const float LOG2E = 1.4426950408889634f;

    u64 kxp[6], kyp[6], kzp[6], vxp[6], vyp[6], vzp[6];

    #pragma unroll
    for (int phase = 0; phase < 2; phase++) {
        const float* wk = phase ? wk1 : wk2;  const float* bk = phase ? bk1 : bk2;
        const float* wv = phase ? wv1 : wv2;  const float* bv = phase ? bv1 : bv2;
        const float* wA = phase ? wq1 : wq3;  const float* bA = phase ? bq1 : bq3;
        const float* wB = phase ? wq2 : wq4;  const float* bB = phase ? bq2 : bq4;

        // Combined g weights, log2(e) pre-folded.
        float wg[9], bg[3];
        #pragma unroll
        for (int c = 0; c < 3; c++) {
            wg[c*3+0] = (wA[c*3+0] + wB[c*3+0]) * LOG2E;
            wg[c*3+1] = (wA[c*3+1] + wB[c*3+1]) * LOG2E;
            wg[c*3+2] = (wA[c*3+2] + wB[c*3+2]) * LOG2E;
            bg[c]     = (bA[c] + bB[c]) * LOG2E;
        }

        {   // Packed K/V of this thread's 12 j's (6 pairs) from x.
            float xs[3 * JP];
            const float4* xp = (const float4*)(x + 3 * j0);   // 144B*t aligned
            #pragma unroll
            for (int q = 0; q < (3 * JP) / 4; q++) {
                float4 f = xp[q];
                xs[4*q] = f.x; xs[4*q+1] = f.y; xs[4*q+2] = f.z; xs[4*q+3] = f.w;
            }
            #pragma unroll
            for (int p = 0; p < 6; p++) {
                float X0 = xs[6*p+0], X1 = xs[6*p+1], X2 = xs[6*p+2];
                float Y0 = xs[6*p+3], Y1 = xs[6*p+4], Y2 = xs[6*p+5];
                kxp[p] = pk2(bk[0] + wk[0]*X0 + wk[1]*X1 + wk[2]*X2,
                             bk[0] + wk[0]*Y0 + wk[1]*Y1 + wk[2]*Y2);
                kyp[p] = pk2(bk[1] + wk[3]*X0 + wk[4]*X1 + wk[5]*X2,
                             bk[1] + wk[3]*Y0 + wk[4]*Y1 + wk[5]*Y2);
                kzp[p] = pk2(bk[2] + wk[6]*X0 + wk[7]*X1 + wk[8]*X2,
                             bk[2] + wk[6]*Y0 + wk[7]*Y1 + wk[8]*Y2);
                vxp[p] = pk2(bv[0] + wv[0]*X0 + wv[1]*X1 + wv[2]*X2,
                             bv[0] + wv[0]*Y0 + wv[1]*Y1 + wv[2]*Y2);
                vyp[p] = pk2(bv[1] + wv[3]*X0 + wv[4]*X1 + wv[5]*X2,
                             bv[1] + wv[3]*Y0 + wv[4]*Y1 + wv[5]*Y2);
                vzp[p] = pk2(bv[2] + wv[6]*X0 + wv[7]*X1 + wv[8]*X2,
                             bv[2] + wv[6]*Y0 + wv[7]*Y1 + wv[8]*Y2);
            }
        }

        // Every warp covers every row with its own j-slice; fully independent.
        for (int i = r0; i < r1; i++) {
            float X0 = __ldg(x + 3*i), X1 = __ldg(x + 3*i + 1), X2 = __ldg(x + 3*i + 2);
            float gxs = bg[0] + wg[0]*X0 + wg[1]*X1 + wg[2]*X2;
            float gys = bg[1] + wg[3]*X0 + wg[4]*X1 + wg[5]*X2;
            float gzs = bg[2] + wg[6]*X0 + wg[7]*X1 + wg[8]*X2;
            u64 gx = pk2(gxs, gxs), gy = pk2(gys, gys), gz = pk2(gzs, gzs);

            u64 sum = 0, ax = 0, ay = 0, az = 0;
            #pragma unroll
            for (int p = 0; p < 6; p++) {
                u64 lg = fma2_(gx, kxp[p], fma2_(gy, kyp[p], mul2_(gz, kzp[p])));
                float l0, l1;  upk2(lg, l0, l1);
                u64 e2 = pk2(ex2(l0), ex2(l1));
                sum = add2_(sum, e2);
                ax  = fma2_(e2, vxp[p], ax);
                ay  = fma2_(e2, vyp[p], ay);
                az  = fma2_(e2, vzp[p], az);
            }
            float r0a, r1a, r2a, r3a, hi;
            upk2(sum, r0a, hi); r0a += hi;
            upk2(ax,  r1a, hi); r1a += hi;
            upk2(ay,  r2a, hi); r2a += hi;
            upk2(az,  r3a, hi); r3a += hi;

            // Private warp tree (5 steps x 4 quantities). No cross-warp sync.
            #pragma unroll
            for (int o = 16; o > 0; o >>= 1) {
                r0a += __shfl_xor_sync(0xffffffffu, r0a, o);
                r1a += __shfl_xor_sync(0xffffffffu, r1a, o);
                r2a += __shfl_xor_sync(0xffffffffu, r2a, o);
                r3a += __shfl_xor_sync(0xffffffffu, r3a, o);
            }
            if (l == 0) {
                float4 p; p.x = r0a; p.y = r1a; p.z = r2a; p.w = r3a;
                ps[phase][i - r0][w] = p;
            }
        }
    }

    // In-block combine (replaces the combine kernel). ONE barrier total.
    __syncthreads();
    if (t < nr) {
        int i = r0 + t;

        float s2 = 0.f, a2x = 0.f, a2y = 0.f, a2z = 0.f;
        #pragma unroll
        for (int ww = 0; ww < NW; ww++) {
            float4 p = ps[0][t][ww];
            s2 += p.x; a2x += p.y; a2y += p.z; a2z += p.w;
        }
        float inv2 = 1.0f / s2;

        float s1 = 0.f, a1x = 0.f, a1y = 0.f, a1z = 0.f;
        #pragma unroll
        for (int ww = 0; ww < NW; ww++) {
            float4 p = ps[1][t][ww];
            s1 += p.x; a1x += p.y; a1y += p.z; a1z += p.w;
        }
        float inv1 = 1.0f / s1;

        // g1 row (combined q1+q2), log2e-scaled, for the writer's recompute.
        float X0 = x[3*i], X1 = x[3*i+1], X2 = x[3*i+2];
        float g1[3];
        #pragma unroll
        for (int c = 0; c < 3; c++) {
            g1[c] = ((bq1[c] + bq2[c])
                  + (wq1[c*3+0] + wq2[c*3+0]) * X0
                  + (wq1[c*3+1] + wq2[c*3+1]) * X1
                  + (wq1[c*3+2] + wq2[c*3+2]) * X2) * LOG2E;
        }
        float4 m; m.x = g1[0]; m.y = g1[1]; m.z = g1[2]; m.w = inv1;
        d_rowmeta[i] = m;

        // b_i = Wb((a1@v1)_i + y2_i) + bb
        float y0 = a1x * inv1 + a2x * inv2;
        float y1 = a1y * inv1 + a2y * inv2;
        float yz = a1z * inv1 + a2z * inv2;
        #pragma unroll
        for (int c = 0; c < 3; c++)
            b_out[i*3+c] = bb[c] + wb[c*3+0]*y0 + wb[c*3+1]*y1 + wb[c*3+2]*yz;
    }
}

// ---------------------------------------------------------------------------
// Kernel W: streaming a1 writer (R9-proven form, untouched). Zero smem /
//   shfl / barriers. Interleaved ownership: thread t owns j-pairs
//   {2t + s*2048}; STG.64 lanes 8B-consecutive -> perfect 128B wavefronts.
// ---------------------------------------------------------------------------
__global__ void __launch_bounds__(TW, 1) write_kernel(
    const float* __restrict__ x,
    const float* __restrict__ wk1, const float* __restrict__ bk1,
    float* __restrict__ a_out)     // [N, N]
{
    const int t  = threadIdx.x;
    const int r0 = (int)(((long long)N * blockIdx.x) / GRID);
    const int r1 = (int)(((long long)N * (blockIdx.x + 1)) / GRID);
    const int nr = r1 - r0;

    // K1 for the 6 owned j's: j = 2t + s*2048 + {0,1}, s = 0..2.
    float kx[6], ky[6], kz[6];
    #pragma unroll
    for (int s = 0; s < 3; s++) {
        int jbase = 2 * t + s * 2048;
        #pragma unroll
        for (int h = 0; h < 2; h++) {
            int j = jbase + h;
            float X0 = x[3*j], X1 = x[3*j+1], X2 = x[3*j+2];
            kx[2*s+h] = bk1[0] + wk1[0]*X0 + wk1[1]*X1 + wk1[2]*X2;
            ky[2*s+h] = bk1[1] + wk1[3]*X0 + wk1[4]*X1 + wk1[5]*X2;
            kz[2*s+h] = bk1[2] + wk1[6]*X0 + wk1[7]*X1 + wk1[8]*X2;
        }
    }

    for (int ii = 0; ii < nr; ii += 4) {
        float4 m[4];
        int    iv[4];
        #pragma unroll
        for (int rr = 0; rr < 4; rr++) {
            int lcl = (ii + rr < nr) ? ii + rr : nr - 1;  // clamp (benign dup)
            iv[rr] = r0 + lcl;
            m[rr]  = d_rowmeta[iv[rr]];                   // broadcast LDG
        }
        #pragma unroll
        for (int rr = 0; rr < 4; rr++) {
            const float gx = m[rr].x, gy = m[rr].y, gz = m[rr].z, inv = m[rr].w;
            float* rowp = a_out + (size_t)iv[rr] * N + 2 * t;
            #pragma unroll
            for (int s = 0; s < 3; s++) {
                float l0 = fmaf(gx, kx[2*s+0], fmaf(gy, ky[2*s+0], gz * kz[2*s+0]));
                float l1 = fmaf(gx, kx[2*s+1], fmaf(gy, ky[2*s+1], gz * kz[2*s+1]));
                float2 o;
                o.x = ex2(l0) * inv;
                o.y = ex2(l1) * inv;
                __stcs((float2*)(rowp + s * 2048), o);    // evict-first stream
            }
        }
    }
}

// ---------------------------------------------------------------------------
// Two launches: reduce(+combine) -> write.
// Output layout: a1 [N*N] followed by b [N*3].
// ---------------------------------------------------------------------------
extern "C" void kernel_launch(void* const* d_in, const int* in_sizes, int n_in,
                              void* d_out, int out_size)
{
    const float* x   = (const float*)d_in[0];
    const float* wq1 = (const float*)d_in[1];
    const float* bq1 = (const float*)d_in[2];
    const float* wq2 = (const float*)d_in[3];
    const float* bq2 = (const float*)d_in[4];
    const float* wq3 = (const float*)d_in[5];
    const float* bq3 = (const float*)d_in[6];
    const float* wq4 = (const float*)d_in[7];
    const float* bq4 = (const float*)d_in[8];
    const float* wk1 = (const float*)d_in[9];
    const float* bk1 = (const float*)d_in[10];
    const float* wk2 = (const float*)d_in[11];
    const float* bk2 = (const float*)d_in[12];
    const float* wv1 = (const float*)d_in[13];
    const float* bv1 = (const float*)d_in[14];
    const float* wv2 = (const float*)d_in[15];
    const float* bv2 = (const float*)d_in[16];
    const float* wb  = (const float*)d_in[17];
    const float* bb  = (const float*)d_in[18];

    float* out = (float*)d_out;
    float* a1  = out;                      // [N, N]
    float* b   = out + (size_t)N * N;      // [N, 3]

    reduce_kernel<<<GRID, TP>>>(
        x, wq1, bq1, wq2, bq2, wq3, bq3, wq4, bq4,
        wk1, bk1, wk2, bk2, wv1, bv1, wv2, bv2,
        wb, bb, b);

    write_kernel<<<GRID, TW>>>(x, wk1, bk1, a1);
}

// round 16
// speedup vs baseline: 1.5806x; 1.0766x over previous
#include <cuda_runtime.h>

// Problem constants
#define N      6144
#define GRID   148      // one block per SM
#define TP     512      // 16 warps
#define NW     16
#define MAXR   48
#define CH     8        // rows per chunk in the merged section

typedef unsigned long long u64;

// MUFU.EX2 forced via PTX.
__device__ __forceinline__ float ex2(float v) {
    float r;
    asm("ex2.approx.f32 %0, %1;" : "=f"(r) : "f"(v));
    return r;
}
// Packed f32x2 ops (FFMA2/FADD2/FMUL2 — only reachable via PTX).
__device__ __forceinline__ u64 pk2(float lo, float hi) {
    u64 r; asm("mov.b64 %0, {%1,%2};" : "=l"(r) : "f"(lo), "f"(hi)); return r;
}
__device__ __forceinline__ void upk2(u64 v, float& lo, float& hi) {
    asm("mov.b64 {%0,%1}, %2;" : "=f"(lo), "=f"(hi) : "l"(v));
}
__device__ __forceinline__ u64 fma2_(u64 a, u64 b, u64 c) {
    u64 r; asm("fma.rn.f32x2 %0, %1, %2, %3;" : "=l"(r) : "l"(a), "l"(b), "l"(c)); return r;
}
__device__ __forceinline__ u64 mul2_(u64 a, u64 b) {
    u64 r; asm("mul.rn.f32x2 %0, %1, %2;" : "=l"(r) : "l"(a), "l"(b)); return r;
}
__device__ __forceinline__ u64 add2_(u64 a, u64 b) {
    u64 r; asm("add.rn.f32x2 %0, %1, %2;" : "=l"(r) : "l"(a), "l"(b)); return r;
}

// ---------------------------------------------------------------------------
// ONE kernel. Per block (one per SM, rows [r0,r1)):
//  Sec A: matrix-2 warp-autonomous packed partials (contiguous j slices),
//         one barrier, combine -> y2 rows in smem.
//  Sec B: matrix-1 with INTERLEAVED j-ownership (j = 2t + 1024p), so the same
//         packed K1 registers feed both the partial mainloop and coalesced
//         stores. Chunked (CH rows): partials -> barrier -> combine (inv1,
//         g1 meta, fused b_out) -> barrier -> writes(c) issued back-to-back
//         with partials(c+1) so store drain overlaps FFMA2/EX2 streams.
// ---------------------------------------------------------------------------
__global__ void __launch_bounds__(TP, 1) fused_kernel(
    const float* __restrict__ x,
    const float* __restrict__ wq1, const float* __restrict__ bq1,
    const float* __restrict__ wq2, const float* __restrict__ bq2,
    const float* __restrict__ wq3, const float* __restrict__ bq3,
    const float* __restrict__ wq4, const float* __restrict__ bq4,
    const float* __restrict__ wk1, const float* __restrict__ bk1,
    const float* __restrict__ wk2, const float* __restrict__ bk2,
    const float* __restrict__ wv1, const float* __restrict__ bv1,
    const float* __restrict__ wv2, const float* __restrict__ bv2,
    const float* __restrict__ wb,  const float* __restrict__ bb,
    float* __restrict__ a_out,     // [N, N]
    float* __restrict__ b_out)     // [N, 3]
{
    __shared__ float4 ps[MAXR][NW + 1];   // partials (full-size in A, CH rows in B)
    __shared__ float  y2s[MAXR][3];       // (a2@v2) rows
    __shared__ float4 meta[CH];           // per-chunk: (g1x,g1y,g1z)*log2e, inv1

    const int t  = threadIdx.x;
    const int w  = t >> 5;
    const int l  = t & 31;
    const int r0 = (int)(((long long)N * blockIdx.x) / GRID);
    const int r1 = (int)(((long long)N * (blockIdx.x + 1)) / GRID);
    const int nr = r1 - r0;
    const float LOG2E = 1.4426950408889634f;

    u64 kxp[6], kyp[6], kzp[6], vxp[6], vyp[6], vzp[6];

    // =======================================================================
    // Sec A: matrix 2 (g=q3+q4, k2, v2) -> y2s
    // =======================================================================
    {
        float wg[9], bg[3];
        #pragma unroll
        for (int c = 0; c < 3; c++) {
            wg[c*3+0] = (wq3[c*3+0] + wq4[c*3+0]) * LOG2E;
            wg[c*3+1] = (wq3[c*3+1] + wq4[c*3+1]) * LOG2E;
            wg[c*3+2] = (wq3[c*3+2] + wq4[c*3+2]) * LOG2E;
            bg[c]     = (bq3[c] + bq4[c]) * LOG2E;
        }
        {   // packed K2/V2, contiguous j slice (j0 = 12t), float4 x loads
            float xs[36];
            const float4* xp = (const float4*)(x + 36 * t);
            #pragma unroll
            for (int q = 0; q < 9; q++) {
                float4 f = xp[q];
                xs[4*q] = f.x; xs[4*q+1] = f.y; xs[4*q+2] = f.z; xs[4*q+3] = f.w;
            }
            #pragma unroll
            for (int p = 0; p < 6; p++) {
                float X0 = xs[6*p+0], X1 = xs[6*p+1], X2 = xs[6*p+2];
                float Y0 = xs[6*p+3], Y1 = xs[6*p+4], Y2 = xs[6*p+5];
                kxp[p] = pk2(bk2[0] + wk2[0]*X0 + wk2[1]*X1 + wk2[2]*X2,
                             bk2[0] + wk2[0]*Y0 + wk2[1]*Y1 + wk2[2]*Y2);
                kyp[p] = pk2(bk2[1] + wk2[3]*X0 + wk2[4]*X1 + wk2[5]*X2,
                             bk2[1] + wk2[3]*Y0 + wk2[4]*Y1 + wk2[5]*Y2);
                kzp[p] = pk2(bk2[2] + wk2[6]*X0 + wk2[7]*X1 + wk2[8]*X2,
                             bk2[2] + wk2[6]*Y0 + wk2[7]*Y1 + wk2[8]*Y2);
                vxp[p] = pk2(bv2[0] + wv2[0]*X0 + wv2[1]*X1 + wv2[2]*X2,
                             bv2[0] + wv2[0]*Y0 + wv2[1]*Y1 + wv2[2]*Y2);
                vyp[p] = pk2(bv2[1] + wv2[3]*X0 + wv2[4]*X1 + wv2[5]*X2,
                             bv2[1] + wv2[3]*Y0 + wv2[4]*Y1 + wv2[5]*Y2);
                vzp[p] = pk2(bv2[2] + wv2[6]*X0 + wv2[7]*X1 + wv2[8]*X2,
                             bv2[2] + wv2[6]*Y0 + wv2[7]*Y1 + wv2[8]*Y2);
            }
        }
        for (int i = r0; i < r1; i++) {
            float X0 = __ldg(x + 3*i), X1 = __ldg(x + 3*i + 1), X2 = __ldg(x + 3*i + 2);
            float gxs = bg[0] + wg[0]*X0 + wg[1]*X1 + wg[2]*X2;
            float gys = bg[1] + wg[3]*X0 + wg[4]*X1 + wg[5]*X2;
            float gzs = bg[2] + wg[6]*X0 + wg[7]*X1 + wg[8]*X2;
            u64 gx = pk2(gxs, gxs), gy = pk2(gys, gys), gz = pk2(gzs, gzs);

            u64 sum = 0, ax = 0, ay = 0, az = 0;
            #pragma unroll
            for (int p = 0; p < 6; p++) {
                u64 lg = fma2_(gx, kxp[p], fma2_(gy, kyp[p], mul2_(gz, kzp[p])));
                float l0, l1;  upk2(lg, l0, l1);
                u64 e2 = pk2(ex2(l0), ex2(l1));
                sum = add2_(sum, e2);
                ax  = fma2_(e2, vxp[p], ax);
                ay  = fma2_(e2, vyp[p], ay);
                az  = fma2_(e2, vzp[p], az);
            }
            float r0a, r1a, r2a, r3a, hi;
            upk2(sum, r0a, hi); r0a += hi;
            upk2(ax,  r1a, hi); r1a += hi;
            upk2(ay,  r2a, hi); r2a += hi;
            upk2(az,  r3a, hi); r3a += hi;
            #pragma unroll
            for (int o = 16; o > 0; o >>= 1) {
                r0a += __shfl_xor_sync(0xffffffffu, r0a, o);
                r1a += __shfl_xor_sync(0xffffffffu, r1a, o);
                r2a += __shfl_xor_sync(0xffffffffu, r2a, o);
                r3a += __shfl_xor_sync(0xffffffffu, r3a, o);
            }
            if (l == 0) {
                float4 p4; p4.x = r0a; p4.y = r1a; p4.z = r2a; p4.w = r3a;
                ps[i - r0][w] = p4;
            }
        }
    }
    __syncthreads();
    if (t < nr) {
        float s2 = 0.f, a2x = 0.f, a2y = 0.f, a2z = 0.f;
        #pragma unroll
        for (int ww = 0; ww < NW; ww++) {
            float4 p = ps[t][ww];
            s2 += p.x; a2x += p.y; a2y += p.z; a2z += p.w;
        }
        float inv2 = 1.0f / s2;
        y2s[t][0] = a2x * inv2;
        y2s[t][1] = a2y * inv2;
        y2s[t][2] = a2z * inv2;
    }
    __syncthreads();   // ps reusable, y2s visible

    // =======================================================================
    // Sec B: matrix 1, interleaved ownership j = 2t + 1024p (+{0,1}).
    // =======================================================================
    float wg1[9], bg1[3];
    #pragma unroll
    for (int c = 0; c < 3; c++) {
        wg1[c*3+0] = (wq1[c*3+0] + wq2[c*3+0]) * LOG2E;
        wg1[c*3+1] = (wq1[c*3+1] + wq2[c*3+1]) * LOG2E;
        wg1[c*3+2] = (wq1[c*3+2] + wq2[c*3+2]) * LOG2E;
        bg1[c]     = (bq1[c] + bq2[c]) * LOG2E;
    }
    #pragma unroll
    for (int p = 0; p < 6; p++) {
        int j = 2 * t + p * 1024;       // pair (j, j+1); 3j even -> float2 ok
        const float2* xp = (const float2*)(x + 3 * j);
        float2 f0 = xp[0], f1 = xp[1], f2 = xp[2];
        float X0 = f0.x, X1 = f0.y, X2 = f1.x;
        float Y0 = f1.y, Y1 = f2.x, Y2 = f2.y;
        kxp[p] = pk2(bk1[0] + wk1[0]*X0 + wk1[1]*X1 + wk1[2]*X2,
                     bk1[0] + wk1[0]*Y0 + wk1[1]*Y1 + wk1[2]*Y2);
        kyp[p] = pk2(bk1[1] + wk1[3]*X0 + wk1[4]*X1 + wk1[5]*X2,
                     bk1[1] + wk1[3]*Y0 + wk1[4]*Y1 + wk1[5]*Y2);
        kzp[p] = pk2(bk1[2] + wk1[6]*X0 + wk1[7]*X1 + wk1[8]*X2,
                     bk1[2] + wk1[6]*Y0 + wk1[7]*Y1 + wk1[8]*Y2);
        vxp[p] = pk2(bv1[0] + wv1[0]*X0 + wv1[1]*X1 + wv1[2]*X2,
                     bv1[0] + wv1[0]*Y0 + wv1[1]*Y1 + wv1[2]*Y2);
        vyp[p] = pk2(bv1[1] + wv1[3]*X0 + wv1[4]*X1 + wv1[5]*X2,
                     bv1[1] + wv1[3]*Y0 + wv1[4]*Y1 + wv1[5]*Y2);
        vzp[p] = pk2(bv1[2] + wv1[6]*X0 + wv1[7]*X1 + wv1[8]*X2,
                     bv1[2] + wv1[6]*Y0 + wv1[7]*Y1 + wv1[8]*Y2);
    }

    const int nch = (nr + CH - 1) / CH;

    // --- chunk partials (lambda-free macro-ish via plain loops) ---
    #define PARTIAL_CHUNK(c)                                                    \
    for (int r = 0; r < CH; r++) {                                              \
        int i = r0 + (c) * CH + r;                                              \
        if (i >= r1) break;                                                     \
        float X0 = __ldg(x + 3*i), X1 = __ldg(x + 3*i + 1), X2 = __ldg(x + 3*i + 2); \
        float gxs = bg1[0] + wg1[0]*X0 + wg1[1]*X1 + wg1[2]*X2;                 \
        float gys = bg1[1] + wg1[3]*X0 + wg1[4]*X1 + wg1[5]*X2;                 \
        float gzs = bg1[2] + wg1[6]*X0 + wg1[7]*X1 + wg1[8]*X2;                 \
        u64 gx = pk2(gxs, gxs), gy = pk2(gys, gys), gz = pk2(gzs, gzs);         \
        u64 sum = 0, ax = 0, ay = 0, az = 0;                                    \
        _Pragma("unroll")                                                       \
        for (int p = 0; p < 6; p++) {                                           \
            u64 lg = fma2_(gx, kxp[p], fma2_(gy, kyp[p], mul2_(gz, kzp[p])));   \
            float l0, l1;  upk2(lg, l0, l1);                                    \
            u64 e2 = pk2(ex2(l0), ex2(l1));                                     \
            sum = add2_(sum, e2);                                               \
            ax  = fma2_(e2, vxp[p], ax);                                        \
            ay  = fma2_(e2, vyp[p], ay);                                        \
            az  = fma2_(e2, vzp[p], az);                                        \
        }                                                                       \
        float r0a, r1a, r2a, r3a, hi;                                           \
        upk2(sum, r0a, hi); r0a += hi;                                          \
        upk2(ax,  r1a, hi); r1a += hi;                                          \
        upk2(ay,  r2a, hi); r2a += hi;                                          \
        upk2(az,  r3a, hi); r3a += hi;                                          \
        _Pragma("unroll")                                                       \
        for (int o = 16; o > 0; o >>= 1) {                                      \
            r0a += __shfl_xor_sync(0xffffffffu, r0a, o);                        \
            r1a += __shfl_xor_sync(0xffffffffu, r1a, o);                        \
            r2a += __shfl_xor_sync(0xffffffffu, r2a, o);                        \
            r3a += __shfl_xor_sync(0xffffffffu, r3a, o);                        \
        }                                                                       \
        if (l == 0) {                                                           \
            float4 p4; p4.x = r0a; p4.y = r1a; p4.z = r2a; p4.w = r3a;          \
            ps[r][w] = p4;                                                      \
        }                                                                       \
    }

    // --- chunk combine: inv1 + g1 meta + fused b_out ---
    #define COMBINE_CHUNK(c)                                                    \
    if (t < CH && (c) * CH + t < nr) {                                          \
        int i = r0 + (c) * CH + t;                                              \
        float s1 = 0.f, a1x = 0.f, a1y = 0.f, a1z = 0.f;                        \
        _Pragma("unroll")                                                       \
        for (int ww = 0; ww < NW; ww++) {                                       \
            float4 p = ps[t][ww];                                               \
            s1 += p.x; a1x += p.y; a1y += p.z; a1z += p.w;                      \
        }                                                                       \
        float inv1 = 1.0f / s1;                                                 \
        float X0 = x[3*i], X1 = x[3*i+1], X2 = x[3*i+2];                        \
        float4 m;                                                               \
        m.x = bg1[0] + wg1[0]*X0 + wg1[1]*X1 + wg1[2]*X2;                       \
        m.y = bg1[1] + wg1[3]*X0 + wg1[4]*X1 + wg1[5]*X2;                       \
        m.z = bg1[2] + wg1[6]*X0 + wg1[7]*X1 + wg1[8]*X2;                       \
        m.w = inv1;                                                             \
        meta[t] = m;                                                            \
        int lr = (c) * CH + t;                                                  \
        float y0 = a1x * inv1 + y2s[lr][0];                                     \
        float y1 = a1y * inv1 + y2s[lr][1];                                     \
        float yz = a1z * inv1 + y2s[lr][2];                                     \
        _Pragma("unroll")                                                       \
        for (int cc = 0; cc < 3; cc++)                                          \
            b_out[i*3+cc] = bb[cc] + wb[cc*3+0]*y0 + wb[cc*3+1]*y1 + wb[cc*3+2]*yz; \
    }

    // --- chunk writes: recompute e from resident K1, coalesced STG.64 ---
    #define WRITE_CHUNK(c)                                                      \
    for (int r = 0; r < CH; r++) {                                              \
        int i = r0 + (c) * CH + r;                                              \
        if (i >= r1) break;                                                     \
        float4 m = meta[r];                                                     \
        u64 gx = pk2(m.x, m.x), gy = pk2(m.y, m.y), gz = pk2(m.z, m.z);         \
        u64 iv2 = pk2(m.w, m.w);                                                \
        float* rowp = a_out + (size_t)i * N + 2 * t;                            \
        _Pragma("unroll")                                                       \
        for (int p = 0; p < 6; p++) {                                           \
            u64 lg = fma2_(gx, kxp[p], fma2_(gy, kyp[p], mul2_(gz, kzp[p])));   \
            float l0, l1;  upk2(lg, l0, l1);                                    \
            u64 o2 = mul2_(pk2(ex2(l0), ex2(l1)), iv2);                         \
            float2 o;  upk2(o2, o.x, o.y);                                      \
            __stcs((float2*)(rowp + p * 1024), o);                              \
        }                                                                       \
    }

    PARTIAL_CHUNK(0)
    __syncthreads();
    COMBINE_CHUNK(0)
    __syncthreads();
    for (int c = 1; c < nch; c++) {
        WRITE_CHUNK(c - 1)      // overlaps (in the warp mix) with...
        PARTIAL_CHUNK(c)        // ...the next chunk's partial math
        __syncthreads();
        COMBINE_CHUNK(c)
        __syncthreads();
    }
    WRITE_CHUNK(nch - 1)

    #undef PARTIAL_CHUNK
    #undef COMBINE_CHUNK
    #undef WRITE_CHUNK
}

// ---------------------------------------------------------------------------
// ONE launch. Output layout: a1 [N*N] followed by b [N*3].
// ---------------------------------------------------------------------------
extern "C" void kernel_launch(void* const* d_in, const int* in_sizes, int n_in,
                              void* d_out, int out_size)
{
    const float* x   = (const float*)d_in[0];
    const float* wq1 = (const float*)d_in[1];
    const float* bq1 = (const float*)d_in[2];
    const float* wq2 = (const float*)d_in[3];
    const float* bq2 = (const float*)d_in[4];
    const float* wq3 = (const float*)d_in[5];
    const float* bq3 = (const float*)d_in[6];
    const float* wq4 = (const float*)d_in[7];
    const float* bq4 = (const float*)d_in[8];
    const float* wk1 = (const float*)d_in[9];
    const float* bk1 = (const float*)d_in[10];
    const float* wk2 = (const float*)d_in[11];
    const float* bk2 = (const float*)d_in[12];
    const float* wv1 = (const float*)d_in[13];
    const float* bv1 = (const float*)d_in[14];
    const float* wv2 = (const float*)d_in[15];
    const float* bv2 = (const float*)d_in[16];
    const float* wb  = (const float*)d_in[17];
    const float* bb  = (const float*)d_in[18];

    float* out = (float*)d_out;
    float* a1  = out;                      // [N, N]
    float* b   = out + (size_t)N * N;      // [N, 3]

    fused_kernel<<<GRID, TP>>>(
        x, wq1, bq1, wq2, bq2, wq3, bq3, wq4, bq4,
        wk1, bk1, wk2, bk2, wv1, bv1, wv2, bv2,
        wb, bb, a1, b);
}